// round 11
// baseline (speedup 1.0000x reference)
#include <cuda_runtime.h>
#include <math.h>

// ARIMA sliding-window loss, collapsed to:
//   err[t] = y[t+33] - K1*FIR(g, win) + M1q*sum - K2q*sqrt(32*sq - sum^2 + 1024*eps)
//   loss   = (sum(y[:33]^2) + sum(err^2)) / S
// Warp-autonomous blocks: TPB=32, TILE=256, 4096 blocks. No __syncthreads in
// the hot path — each warp stages its own tile (coalesced, swizzled) and runs
// a two-phase 32-tap FIR (RPT=8) fully register-resident.

#define PW    32
#define T0    33
#define EPSF  1e-5f
#define TPB   32
#define RPT   8
#define TILE  (TPB * RPT)        // 256 t per block
#define NCHUNK 73                // 16B chunks staged: floats y[tb .. tb+291]
#define MAXB  8192

#define SWZ(b) ((b) ^ (((b) >> 3) & 0x70))

__device__ float        g_part[MAXB];
__device__ unsigned int g_c1[128];   // group counters (wrap -> self-reset)
__device__ unsigned int g_c2 = 0;    // master counter

__device__ __forceinline__ float sqrt_apx(float x) {
    float r; asm("sqrt.approx.f32 %0, %1;" : "=f"(r) : "f"(x)); return r;
}

__global__ void __launch_bounds__(TPB, 28) arima_fused(
    const float* __restrict__ y,
    const float* __restrict__ w,
    const float* __restrict__ ab,
    const float* __restrict__ rw_,
    const float* __restrict__ rb_,
    float* __restrict__ out,
    int T, int S)
{
    __shared__ __align__(128) float sy[304];   // swizzled y[tb + i], 74 chunks + pad
    __shared__ __align__(16)  float sg[PW];

    const float4* sg4 = (const float4*)sg;
    const int tid = threadIdx.x;               // 0..31
    const int bid = blockIdx.x;
    const int tb  = bid * TILE;
    const int nb  = gridDim.x;

    // FIR taps (one lane per tap)
    {
        float wj  = w[tid];
        float wj1 = (tid < PW - 1) ? w[tid + 1] : 0.0f;
        float gv  = wj - wj1;
        if (tid == PW - 2) gv -= 1.0f;
        if (tid == PW - 1) gv += 1.0f;
        sg[tid] = gv;
    }
    // Scalar constants, computed redundantly per lane (L1-hit loads)
    const float rw = rw_[0], rb = rb_[0], b = ab[0], w0 = w[0];
    const float rdenom = __fdividef(1.0f, rw + EPSF * EPSF);
    const float K1  = rw * rdenom;
    const float K2q = ((w0 * rb - rb + b) * rdenom) * (1.0f / 32.0f);
    const float M1q = fmaf(K1, w0, -1.0f) * (1.0f / 32.0f);
    const float C0  = 1024.0f * EPSF;

    // Coalesced stage, swizzled store: chunk i holds y[tb+4i .. +3]
    {
        const float4* y4 = (const float4*)(y + tb);
        #pragma unroll
        for (int c = 0; c < 3; c++) {
            int i = tid + 32 * c;
            if (i < NCHUNK) {
                int gf = tb + 4 * i;
                float4 v;
                if (gf + 3 < S) v = y4[i];
                else {
                    v.x = (gf     < S) ? y[gf]     : 0.f;
                    v.y = (gf + 1 < S) ? y[gf + 1] : 0.f;
                    v.z = (gf + 2 < S) ? y[gf + 2] : 0.f;
                    v.w = (gf + 3 < S) ? y[gf + 3] : 0.f;
                }
                *(float4*)((char*)sy + SWZ(16 * i)) = v;
            }
        }
    }
    __syncwarp();

    const int t0 = tb + tid * RPT;       // xv[m] = y[t0+m]

    float f[RPT];
    #pragma unroll
    for (int r = 0; r < RPT; r++) f[r] = 0.0f;
    float sum = 0.f, sq = 0.f;
    float old_[RPT];

    // ---- Phase A: xv[0..23], taps 0..15 ----
    {
        float xa[24];
        #pragma unroll
        for (int c = 0; c < 6; c++) {
            int k = 2 * tid + c;
            float4 v = *(const float4*)((const char*)sy + SWZ(16 * k));
            xa[4*c+0] = v.x; xa[4*c+1] = v.y; xa[4*c+2] = v.z; xa[4*c+3] = v.w;
        }
        #pragma unroll
        for (int r = 0; r < RPT; r++) old_[r] = xa[r];
        #pragma unroll
        for (int c = 0; c < 4; c++) {
            float4 gc = sg4[c];
            const float ge[4] = {gc.x, gc.y, gc.z, gc.w};
            #pragma unroll
            for (int e = 0; e < 4; e++) {
                const int j = 4 * c + e;
                float xj = xa[1 + j];
                sum += xj;
                sq   = fmaf(xj, xj, sq);
                #pragma unroll
                for (int r = 0; r < RPT; r++)
                    f[r] = fmaf(ge[e], xa[1 + j + r], f[r]);
            }
        }
        #pragma unroll
        for (int m = 17; m < 24; m++) {      // xv[17..23]
            sum += xa[m];
            sq   = fmaf(xa[m], xa[m], sq);
        }
    }

    // ---- Phase B: xv[16..43], taps 16..31, epilogue ----
    float esum_f = 0.0f;
    {
        float xb[28];                        // xb[i] = xv[16+i]
        #pragma unroll
        for (int c = 0; c < 7; c++) {
            int k = 2 * tid + 4 + c;
            float4 v = *(const float4*)((const char*)sy + SWZ(16 * k));
            xb[4*c+0] = v.x; xb[4*c+1] = v.y; xb[4*c+2] = v.z; xb[4*c+3] = v.w;
        }
        #pragma unroll
        for (int c = 4; c < 8; c++) {
            float4 gc = sg4[c];
            const float ge[4] = {gc.x, gc.y, gc.z, gc.w};
            #pragma unroll
            for (int e = 0; e < 4; e++) {
                const int j = 4 * c + e;
                #pragma unroll
                for (int r = 0; r < RPT; r++)
                    f[r] = fmaf(ge[e], xb[j + r - 15], f[r]);
            }
        }
        #pragma unroll
        for (int m = 8; m <= 16; m++) {      // xv[24..32]
            sum += xb[m];
            sq   = fmaf(xb[m], xb[m], sq);
        }

        if (t0 + RPT <= T) {
            #pragma unroll
            for (int r = 0; r < RPT; r++) {
                if (r > 0) {
                    float xn = xb[16 + r], xo = old_[r];
                    sum += xn - xo;
                    sq   = fmaf(xn, xn, sq);
                    sq   = fmaf(-xo, xo, sq);
                }
                float sa  = fmaf(-sum, sum, fmaf(32.0f, sq, C0));
                float sd  = sqrt_apx(sa);
                float err = fmaf(-K2q, sd, fmaf(M1q, sum, fmaf(-K1, f[r], xb[17 + r])));
                esum_f = fmaf(err, err, esum_f);
            }
        } else {
            #pragma unroll
            for (int r = 0; r < RPT; r++) {
                if (r > 0) {
                    float xn = xb[16 + r], xo = old_[r];
                    sum += xn - xo;
                    sq   = fmaf(xn, xn, sq);
                    sq   = fmaf(-xo, xo, sq);
                }
                if (t0 + r < T) {
                    float sa  = fmaf(-sum, sum, fmaf(32.0f, sq, C0));
                    float sd  = sqrt_apx(sa);
                    float err = fmaf(-K2q, sd, fmaf(M1q, sum, fmaf(-K1, f[r], xb[17 + r])));
                    esum_f = fmaf(err, err, esum_f);
                }
            }
        }
    }

    // Warp reduction (float; per-block partial)
    #pragma unroll
    for (int o = 16; o > 0; o >>= 1)
        esum_f += __shfl_xor_sync(0xffffffffu, esum_f, o);

    // Two-level last-block detection (group = 64 blocks -> pipelined atomics)
    int last = 0;
    if (tid == 0) {
        g_part[bid] = esum_f;
        __threadfence();
        int grp   = bid >> 6;
        int gbase = grp << 6;
        unsigned gsz = (unsigned)min(64, nb - gbase);
        unsigned pos = atomicInc(&g_c1[grp], gsz - 1u);
        if (pos == gsz - 1u) {
            unsigned ngr = (unsigned)((nb + 63) >> 6);
            unsigned p2  = atomicInc(&g_c2, ngr - 1u);
            last = (p2 == ngr - 1u);
        }
    }
    last = __shfl_sync(0xffffffffu, last, 0);

    if (last) {
        __threadfence();
        double s0 = 0.0, s1 = 0.0, s2 = 0.0, s3 = 0.0;
        for (int i = tid; i < nb; i += 128) {
            s0 += (double)g_part[i];
            int i1 = i + 32, i2 = i + 64, i3 = i + 96;
            if (i1 < nb) s1 += (double)g_part[i1];
            if (i2 < nb) s2 += (double)g_part[i2];
            if (i3 < nb) s3 += (double)g_part[i3];
        }
        double s = (s0 + s1) + (s2 + s3);
        for (int i = tid; i < T0; i += 32) { double v = (double)y[i]; s += v * v; }
        #pragma unroll
        for (int o = 16; o > 0; o >>= 1)
            s += __shfl_xor_sync(0xffffffffu, s, o);
        if (tid == 0) out[0] = (float)(s / (double)S);
    }
}

extern "C" void kernel_launch(void* const* d_in, const int* in_sizes, int n_in,
                              void* d_out, int out_size)
{
    const float* y  = (const float*)d_in[0];
    const float* w  = (const float*)d_in[1];
    const float* ab = (const float*)d_in[2];
    const float* rw = (const float*)d_in[3];
    const float* rb = (const float*)d_in[4];
    int S = in_sizes[0];
    int T = S - T0;
    int nblocks = (T + TILE - 1) / TILE;   // S=1M -> 4096 warp-blocks
    if (nblocks > MAXB) nblocks = MAXB;
    arima_fused<<<nblocks, TPB>>>(y, w, ab, rw, rb, (float*)d_out, T, S);
}

// round 12
// speedup vs baseline: 1.8221x; 1.8221x over previous
#include <cuda_runtime.h>
#include <math.h>

// ARIMA sliding-window loss, collapsed to:
//   err[t] = y[t+33] - K1*FIR(g, win) + M1q*sum - K2q*sqrt(32*sq - sum^2 + 1024*eps)
//   loss   = (sum(y[:33]^2) + sum(err^2)) / S
// Geometry chosen so full register residency and single-wave coexist:
// TPB=128, RPT=12, TILE=1536 -> 683 blocks, __launch_bounds__(128,5) -> 102-reg
// budget. Single-phase FIR (12 chains x 32 taps), 12 aligned LDS.128 per thread
// (48B lane stride = conflict-free, no swizzle), single code path (masked tail).

#define PW    32
#define T0    33
#define EPSF  1e-5f
#define TPB   128
#define RPT   12
#define TILE  (TPB * RPT)        // 1536 t per block
#define WIN   (RPT + 36)         // 48 window floats per thread
#define STAGE 1600               // floats staged: y[tb .. tb+1584), padded
#define NCHUNK 396               // 16B chunks (1584/4)
#define MAXB  2048

__device__ float        g_part[MAXB];
__device__ unsigned int g_ctr = 0;   // atomicInc wraps to 0 each launch

__device__ __forceinline__ float sqrt_apx(float x) {
    float r; asm("sqrt.approx.f32 %0, %1;" : "=f"(r) : "f"(x)); return r;
}

__global__ void __launch_bounds__(TPB, 5) arima_fused(
    const float* __restrict__ y,
    const float* __restrict__ w,
    const float* __restrict__ ab,
    const float* __restrict__ rw_,
    const float* __restrict__ rb_,
    float* __restrict__ out,
    int T, int S)
{
    __shared__ __align__(16) float sy[STAGE];
    __shared__ __align__(16) float sg[PW];
    __shared__ float  sc[3];
    __shared__ double sred[TPB / 32];
    __shared__ int    isLast;

    const float4* sy4 = (const float4*)sy;
    const float4* sg4 = (const float4*)sg;
    const int tid = threadIdx.x;
    const int bid = blockIdx.x;
    const int tb  = bid * TILE;

    // FIR taps from ar_weight + differencing structure
    if (tid < PW) {
        float wj  = w[tid];
        float wj1 = (tid < PW - 1) ? w[tid + 1] : 0.0f;
        float gv  = wj - wj1;
        if (tid == PW - 2) gv -= 1.0f;   // g[30] = w30 - w31 - 1
        if (tid == PW - 1) gv += 1.0f;   // g[31] = w31 + 1
        sg[tid] = gv;
    }
    if (tid == 0) {
        float rw = rw_[0], rb = rb_[0], b = ab[0], w0 = w[0];
        float denom = rw + EPSF * EPSF;
        float K1 = rw / denom;
        float K2 = (w0 * rb - rb + b) / denom;
        float M1 = fmaf(K1, w0, -1.0f);
        sc[0] = K1;
        sc[1] = K2 * (1.0f / 32.0f);      // K2q
        sc[2] = M1 * (1.0f / 32.0f);      // M1q
    }

    // Coalesced stage: chunk i holds y[tb+4i .. +3]; zero-pad past S
    {
        const float4* y4 = (const float4*)(y + tb);
        #pragma unroll
        for (int c = 0; c < 4; c++) {
            int i = tid + c * TPB;
            if (i < NCHUNK) {
                int gf = tb + 4 * i;
                float4 v;
                if (gf + 3 < S) v = y4[i];
                else {
                    v.x = (gf     < S) ? y[gf]     : 0.f;
                    v.y = (gf + 1 < S) ? y[gf + 1] : 0.f;
                    v.z = (gf + 2 < S) ? y[gf + 2] : 0.f;
                    v.w = (gf + 3 < S) ? y[gf + 3] : 0.f;
                }
                ((float4*)sy)[i] = v;
            }
        }
    }
    __syncthreads();

    const float K1 = sc[0], K2q = sc[1], M1q = sc[2];
    const float C0 = 1024.0f * EPSF;
    const int t0 = tb + tid * RPT;       // xv[m] = y[t0+m]

    // Full window in registers: 12 aligned LDS.128 (chunk = 3*tid + c)
    float xv[WIN];
    #pragma unroll
    for (int c = 0; c < WIN / 4; c++) {
        float4 v = sy4[3 * tid + c];
        xv[4*c + 0] = v.x; xv[4*c + 1] = v.y;
        xv[4*c + 2] = v.z; xv[4*c + 3] = v.w;
    }

    // 12 FIR chains + initial sum/sumsq over xv[1..32]
    float f[RPT];
    #pragma unroll
    for (int r = 0; r < RPT; r++) f[r] = 0.0f;
    float sum = 0.f, sq = 0.f;
    #pragma unroll
    for (int c = 0; c < 8; c++) {
        float4 gc = sg4[c];
        const float ge[4] = {gc.x, gc.y, gc.z, gc.w};
        #pragma unroll
        for (int e = 0; e < 4; e++) {
            const int j = 4 * c + e;
            float xj = xv[1 + j];
            sum += xj;
            sq   = fmaf(xj, xj, sq);
            #pragma unroll
            for (int r = 0; r < RPT; r++)
                f[r] = fmaf(ge[e], xv[1 + j + r], f[r]);
        }
    }

    // Epilogue: single path, tail masked by predicated accumulate
    float esum_f = 0.0f;
    #pragma unroll
    for (int r = 0; r < RPT; r++) {
        if (r > 0) {
            float xn = xv[32 + r], xo = xv[r];
            sum += xn - xo;
            sq   = fmaf(xn, xn, sq);
            sq   = fmaf(-xo, xo, sq);
        }
        float u   = fmaf(-sum, sum, fmaf(32.0f, sq, C0));
        float sd  = sqrt_apx(u);
        float err = fmaf(-K2q, sd, fmaf(M1q, sum, fmaf(-K1, f[r], xv[33 + r])));
        if (t0 + r < T)
            esum_f = fmaf(err, err, esum_f);
    }

    // Block reduction (double from warp level up)
    double esum = (double)esum_f;
    #pragma unroll
    for (int o = 16; o > 0; o >>= 1)
        esum += __shfl_down_sync(0xffffffffu, esum, o);
    if ((tid & 31) == 0) sred[tid >> 5] = esum;
    __syncthreads();
    if (tid == 0) {
        double bs = 0.0;
        #pragma unroll
        for (int i = 0; i < TPB / 32; i++) bs += sred[i];
        g_part[bid] = (float)bs;
        __threadfence();
        unsigned pos = atomicInc(&g_ctr, gridDim.x - 1);
        isLast = (pos == gridDim.x - 1);
    }
    __syncthreads();

    // Last block: deterministic final reduction + head term
    if (isLast) {
        __threadfence();
        double s = 0.0;
        for (int i = tid; i < (int)gridDim.x; i += TPB) s += (double)g_part[i];
        for (int i = tid; i < T0; i += TPB) { double v = (double)y[i]; s += v * v; }
        #pragma unroll
        for (int o = 16; o > 0; o >>= 1)
            s += __shfl_down_sync(0xffffffffu, s, o);
        if ((tid & 31) == 0) sred[tid >> 5] = s;
        __syncthreads();
        if (tid == 0) {
            double tot = 0.0;
            #pragma unroll
            for (int i = 0; i < TPB / 32; i++) tot += sred[i];
            out[0] = (float)(tot / (double)S);
        }
    }
}

extern "C" void kernel_launch(void* const* d_in, const int* in_sizes, int n_in,
                              void* d_out, int out_size)
{
    const float* y  = (const float*)d_in[0];
    const float* w  = (const float*)d_in[1];
    const float* ab = (const float*)d_in[2];
    const float* rw = (const float*)d_in[3];
    const float* rb = (const float*)d_in[4];
    int S = in_sizes[0];
    int T = S - T0;
    int nblocks = (T + TILE - 1) / TILE;   // S=1M -> 683 blocks (single wave @5/SM)
    if (nblocks > MAXB) nblocks = MAXB;
    arima_fused<<<nblocks, TPB>>>(y, w, ab, rw, rb, (float*)d_out, T, S);
}